// round 8
// baseline (speedup 1.0000x reference)
#include <cuda_runtime.h>
#include <cuda_bf16.h>
#include <cstdint>
#include <math.h>

// Problem constants
#define BATCH   4
#define S_LEN   4096
#define EMB     1024
#define HEADS   16
#define HD      64
#define M_TOK   (BATCH * S_LEN)   // 16384
#define BH      (BATCH * HEADS)   // 64
#define KV_SPLIT 8

// ---------------------------------------------------------------------------
// Scratch (device globals: allocation-free, rule-compliant)
// ---------------------------------------------------------------------------
__device__ float g_q[(size_t)BH * S_LEN * HD];     // [b,h,s,d] phi(q)
__device__ float g_k[(size_t)BH * S_LEN * HD];     // [b,h,s,d] phi(k)
__device__ float g_v[(size_t)BH * S_LEN * HD];     // [b,h,s,d] v
__device__ float g_KV[BH * HD * HD];               // [bh, d, e]
__device__ float g_Ksum[BH * HD];                  // [bh, d]

// split-precision bf16 buffers
__device__ __nv_bfloat16 g_xh[(size_t)M_TOK * EMB];
__device__ __nv_bfloat16 g_xl[(size_t)M_TOK * EMB];
__device__ __nv_bfloat16 g_ah[(size_t)M_TOK * EMB];   // attn out hi (token-major)
__device__ __nv_bfloat16 g_al[(size_t)M_TOK * EMB];   // attn out lo
__device__ __nv_bfloat16 g_wh[(size_t)4 * EMB * EMB]; // Wq,Wk,Wv,Wo hi
__device__ __nv_bfloat16 g_wl[(size_t)4 * EMB * EMB]; // Wq,Wk,Wv,Wo lo

// ---------------------------------------------------------------------------
// PTX helpers (sm_100 base target: cp.async / ldmatrix / mma.sync only)
// ---------------------------------------------------------------------------
__device__ __forceinline__ uint32_t smem_u32(const void* p) {
    uint32_t a;
    asm("{ .reg .u64 t; cvta.to.shared.u64 t, %1; cvt.u32.u64 %0, t; }"
        : "=r"(a) : "l"(p));
    return a;
}

__device__ __forceinline__ void cp16(uint32_t dst, const void* src) {
    asm volatile("cp.async.cg.shared.global [%0], [%1], 16;"
                 :: "r"(dst), "l"(src));
}
#define CP_COMMIT()  asm volatile("cp.async.commit_group;" ::: "memory")
#define CP_WAIT2()   asm volatile("cp.async.wait_group 2;" ::: "memory")

__device__ __forceinline__ void ldsm4(uint32_t* r, uint32_t addr) {
    asm volatile("ldmatrix.sync.aligned.m8n8.x4.shared.b16 {%0,%1,%2,%3}, [%4];"
                 : "=r"(r[0]), "=r"(r[1]), "=r"(r[2]), "=r"(r[3]) : "r"(addr));
}

__device__ __forceinline__ void mma_bf16(float* c, const uint32_t* a, const uint32_t* b) {
    asm volatile(
        "mma.sync.aligned.m16n8k16.row.col.f32.bf16.bf16.f32 "
        "{%0,%1,%2,%3}, {%4,%5,%6,%7}, {%8,%9}, {%0,%1,%2,%3};"
        : "+f"(c[0]), "+f"(c[1]), "+f"(c[2]), "+f"(c[3])
        : "r"(a[0]), "r"(a[1]), "r"(a[2]), "r"(a[3]), "r"(b[0]), "r"(b[1]));
}

// ---------------------------------------------------------------------------
// fp32 -> (hi, lo) bf16 split conversion (grid-stride over float4)
// ---------------------------------------------------------------------------
__global__ void cvt_split(const float4* __restrict__ in,
                          uint2* __restrict__ hi, uint2* __restrict__ lo, int n4)
{
    int i = blockIdx.x * blockDim.x + threadIdx.x;
    if (i >= n4) return;
    float4 v = in[i];
    __nv_bfloat162 h0 = __floats2bfloat162_rn(v.x, v.y);
    __nv_bfloat162 h1 = __floats2bfloat162_rn(v.z, v.w);
    float2 f0 = __bfloat1622float2(h0);
    float2 f1 = __bfloat1622float2(h1);
    __nv_bfloat162 l0 = __floats2bfloat162_rn(v.x - f0.x, v.y - f0.y);
    __nv_bfloat162 l1 = __floats2bfloat162_rn(v.z - f1.x, v.w - f1.y);
    uint2 hu, lu;
    hu.x = *(uint32_t*)&h0; hu.y = *(uint32_t*)&h1;
    lu.x = *(uint32_t*)&l0; lu.y = *(uint32_t*)&l1;
    hi[i] = hu;
    lo[i] = lu;
}

// ---------------------------------------------------------------------------
// mma.sync split-bf16 GEMM (TN): C = A[M,1024] * W[N,1024]^T + bias (+phi)
// CTA 128x256, 8 warps (warp tile 64x64, 2x4 warp grid), BK=32,
// 3-stage cp.async pipeline.
// smem per stage: Ah(128x80) Al(128x80) Wh(256x80) Wl(256x80) = 61440 B.
// OUTMODE 0: token-major.  OUTMODE 1: scatter to [b,h,s,d].
// ---------------------------------------------------------------------------
#define ROWB     80
#define A_TILE   (128 * ROWB)                  // 10240
#define W_TILE   (256 * ROWB)                  // 20480
#define STG_BYTES (2 * A_TILE + 2 * W_TILE)    // 61440
#define SMEM_DYN (3 * STG_BYTES)               // 184320

__device__ __forceinline__ void load_stage(
    uint32_t smem_base, int st, int kt,
    const __nv_bfloat16* __restrict__ Ahb, const __nv_bfloat16* __restrict__ Alb,
    const __nv_bfloat16* __restrict__ Whb, const __nv_bfloat16* __restrict__ Wlb,
    int tid)
{
    uint32_t sb = smem_base + st * STG_BYTES;
    const int koff = kt * 32;
    // A tiles: 128 rows x 4 cp16, hi then lo (512 cp16 each -> 2 reps)
#pragma unroll
    for (int rep = 0; rep < 2; rep++) {
        int id  = tid + rep * 256;
        int row = id >> 2;
        int c   = id & 3;
        cp16(sb + row * ROWB + c * 16,          Ahb + (size_t)row * EMB + koff + c * 8);
        cp16(sb + A_TILE + row * ROWB + c * 16, Alb + (size_t)row * EMB + koff + c * 8);
    }
    // W tiles: 256 rows x 4 cp16, hi then lo (1024 cp16 each -> 4 reps)
    uint32_t wb = sb + 2 * A_TILE;
#pragma unroll
    for (int rep = 0; rep < 4; rep++) {
        int id  = tid + rep * 256;
        int row = id >> 2;
        int c   = id & 3;
        cp16(wb + row * ROWB + c * 16,          Whb + (size_t)row * EMB + koff + c * 8);
        cp16(wb + W_TILE + row * ROWB + c * 16, Wlb + (size_t)row * EMB + koff + c * 8);
    }
}

__device__ __forceinline__ void compute_k16(
    uint32_t sa, int k16, int wm, int wn, int lane, float acc[4][8][4])
{
    uint32_t a_h[4][4], a_l[4][4];
    const uint32_t arow = (uint32_t)(wm + (lane & 15));
    const uint32_t acol = (uint32_t)(k16 * 16 + (lane >> 4) * 8) * 2;
#pragma unroll
    for (int mt = 0; mt < 4; mt++) {
        uint32_t ad = sa + (arow + mt * 16) * ROWB + acol;
        ldsm4(a_h[mt], ad);
        ldsm4(a_l[mt], ad + A_TILE);
    }
    const uint32_t wbase = sa + 2 * A_TILE;
    const uint32_t brow = (uint32_t)(wn + ((lane >> 4) * 8) + (lane & 7));
    const uint32_t bcol = (uint32_t)(k16 * 16 + ((lane >> 3) & 1) * 8) * 2;
#pragma unroll
    for (int nt2 = 0; nt2 < 4; nt2++) {
        uint32_t bh[4], bl[4];
        uint32_t bd = wbase + (brow + nt2 * 16) * ROWB + bcol;
        ldsm4(bh, bd);
        ldsm4(bl, bd + W_TILE);
#pragma unroll
        for (int mt = 0; mt < 4; mt++) {
            mma_bf16(acc[mt][nt2 * 2],     a_h[mt], bh);
            mma_bf16(acc[mt][nt2 * 2],     a_h[mt], bl);
            mma_bf16(acc[mt][nt2 * 2],     a_l[mt], bh);
            mma_bf16(acc[mt][nt2 * 2 + 1], a_h[mt], bh + 2);
            mma_bf16(acc[mt][nt2 * 2 + 1], a_h[mt], bl + 2);
            mma_bf16(acc[mt][nt2 * 2 + 1], a_l[mt], bh + 2);
        }
    }
}

template <int OUTMODE, bool PHI>
__global__ void __launch_bounds__(256, 1) mma_gemm(
    const __nv_bfloat16* __restrict__ Ah, const __nv_bfloat16* __restrict__ Al,
    const __nv_bfloat16* __restrict__ Wh, const __nv_bfloat16* __restrict__ Wl,
    const float* __restrict__ bias, float* __restrict__ C)
{
    extern __shared__ char smem[];
    const uint32_t smem_base = smem_u32(smem);
    const int tid  = threadIdx.x;
    const int wid  = tid >> 5;
    const int lane = tid & 31;
    const int bm = blockIdx.y * 128;
    const int bn = blockIdx.x * 256;
    const int wm = (wid & 1) * 64;       // 2 warps in M
    const int wn = (wid >> 1) * 64;      // 4 warps in N

    const __nv_bfloat16* Ahb = Ah + (size_t)bm * EMB;
    const __nv_bfloat16* Alb = Al + (size_t)bm * EMB;
    const __nv_bfloat16* Whb = Wh + (size_t)bn * EMB;
    const __nv_bfloat16* Wlb = Wl + (size_t)bn * EMB;

    float acc[4][8][4] = {};

    // prologue: stages 0,1 for ktiles 0,1
    load_stage(smem_base, 0, 0, Ahb, Alb, Whb, Wlb, tid);
    CP_COMMIT();
    load_stage(smem_base, 1, 1, Ahb, Alb, Whb, Wlb, tid);
    CP_COMMIT();

    const int NKT = EMB / 32;   // 32
    for (int kt = 0; kt < NKT; kt++) {
        if (kt + 2 < NKT)
            load_stage(smem_base, (kt + 2) % 3, kt + 2, Ahb, Alb, Whb, Wlb, tid);
        CP_COMMIT();
        CP_WAIT2();
        __syncthreads();
        uint32_t sa = smem_base + (kt % 3) * STG_BYTES;
        compute_k16(sa, 0, wm, wn, lane, acc);
        compute_k16(sa, 1, wm, wn, lane, acc);
        __syncthreads();
    }

    // epilogue: bias (+phi), store from register accumulators
    const int ln4 = lane >> 2;
    const int lc  = (lane & 3) * 2;
#pragma unroll
    for (int mt = 0; mt < 4; mt++) {
#pragma unroll
        for (int half = 0; half < 2; half++) {
            int m  = bm + wm + mt * 16 + ln4 + half * 8;
            int bb = m >> 12;                // batch (S_LEN=4096)
            int s  = m & (S_LEN - 1);
#pragma unroll
            for (int nt = 0; nt < 8; nt++) {
                int n = bn + wn + nt * 8 + lc;
                float2 bv = *(const float2*)(bias + n);
                float vx = acc[mt][nt][half * 2 + 0] + bv.x;
                float vy = acc[mt][nt][half * 2 + 1] + bv.y;
                if (PHI) {
                    vx = (vx > 0.f) ? vx + 1.f : __expf(vx);
                    vy = (vy > 0.f) ? vy + 1.f : __expf(vy);
                }
                float2 r = make_float2(vx, vy);
                if (OUTMODE == 0) {
                    *(float2*)(C + (size_t)m * EMB + n) = r;
                } else {
                    int h = n >> 6, d = n & 63;
                    *(float2*)(C + (((size_t)(bb * HEADS + h)) * S_LEN + s) * HD + d) = r;
                }
            }
        }
    }
}

// ---------------------------------------------------------------------------
// Zero the KV / Ksum accumulators (device globals persist across graph replays)
// ---------------------------------------------------------------------------
__global__ void zero_kv_kernel()
{
    int i = blockIdx.x * blockDim.x + threadIdx.x;
    if (i < BH * HD * HD) g_KV[i] = 0.f;
    if (i < BH * HD)      g_Ksum[i] = 0.f;
}

// ---------------------------------------------------------------------------
// KV[bh,d,e] = sum_s k_phi[s,d] * v[s,e];  Ksum[bh,d] = sum_s k_phi[s,d]
// ---------------------------------------------------------------------------
__global__ void __launch_bounds__(256) kv_kernel()
{
    const int bh    = blockIdx.x;
    const int split = blockIdx.y;
    const int tid   = threadIdx.x;
    const int te    = tid & 15;
    const int td    = tid >> 4;

    __shared__ float ks[32][64];
    __shared__ float vs[32][64];

    float acc[4][4] = {};
    float ksum[4]   = {};

    const float* kp = g_k + (size_t)bh * S_LEN * HD;
    const float* vp = g_v + (size_t)bh * S_LEN * HD;

    const int sBeg = split * (S_LEN / KV_SPLIT);
    const int sEnd = sBeg + (S_LEN / KV_SPLIT);

    for (int s0 = sBeg; s0 < sEnd; s0 += 32) {
#pragma unroll
        for (int i = 0; i < 2; i++) {
            int id  = tid + i * 256;
            int row = id >> 4;
            int c4  = (id & 15) * 4;
            *(float4*)&ks[row][c4] = *(const float4*)(kp + (size_t)(s0 + row) * HD + c4);
            *(float4*)&vs[row][c4] = *(const float4*)(vp + (size_t)(s0 + row) * HD + c4);
        }
        __syncthreads();
#pragma unroll 4
        for (int s = 0; s < 32; s++) {
            float4 k4 = *(float4*)&ks[s][td * 4];
            float4 v4 = *(float4*)&vs[s][te * 4];
            float kd[4] = {k4.x, k4.y, k4.z, k4.w};
            float ve[4] = {v4.x, v4.y, v4.z, v4.w};
#pragma unroll
            for (int i = 0; i < 4; i++)
#pragma unroll
                for (int j = 0; j < 4; j++)
                    acc[i][j] += kd[i] * ve[j];
            if (te == 0) {
#pragma unroll
                for (int i = 0; i < 4; i++) ksum[i] += kd[i];
            }
        }
        __syncthreads();
    }

    float* kvout = g_KV + (size_t)bh * HD * HD;
#pragma unroll
    for (int i = 0; i < 4; i++)
#pragma unroll
        for (int j = 0; j < 4; j++)
            atomicAdd(&kvout[(td * 4 + i) * HD + te * 4 + j], acc[i][j]);
    if (te == 0) {
#pragma unroll
        for (int i = 0; i < 4; i++)
            atomicAdd(&g_Ksum[bh * HD + td * 4 + i], ksum[i]);
    }
}

// ---------------------------------------------------------------------------
// attn: out = (q_phi @ KV) / (q_phi @ Ksum + eps), written directly as
// split hi/lo bf16 into g_ah/g_al (token-major), feeding the final GEMM.
// ---------------------------------------------------------------------------
__global__ void __launch_bounds__(128) attn_kernel()
{
    const int bh  = blockIdx.y;
    const int s0  = blockIdx.x * 128;
    const int tid = threadIdx.x;
    const int sgrp = tid >> 2;
    const int ech  = (tid & 3) * 16;

    __shared__ float qs[32 * 128];
    __shared__ float kvs[64 * 64];
    __shared__ float ksums[64];

#pragma unroll
    for (int i = 0; i < 8; i++) {
        int id = tid + i * 128;
        *(float4*)&kvs[id * 4] = *(const float4*)(g_KV + (size_t)bh * HD * HD + id * 4);
    }
    if (tid < 64) ksums[tid] = g_Ksum[bh * HD + tid];

    float num[4][16] = {};
    float den[4]     = {};

    const float* qp = g_q + ((size_t)bh * S_LEN + s0) * HD;

    for (int dh = 0; dh < 2; dh++) {
        __syncthreads();
#pragma unroll
        for (int i = 0; i < 8; i++) {
            int id  = tid + i * 128;
            int row = id >> 3;
            int c4  = (id & 7) * 4;
            float4 qv = *(const float4*)(qp + (size_t)row * HD + dh * 32 + c4);
            qs[(c4 + 0) * 128 + row] = qv.x;
            qs[(c4 + 1) * 128 + row] = qv.y;
            qs[(c4 + 2) * 128 + row] = qv.z;
            qs[(c4 + 3) * 128 + row] = qv.w;
        }
        __syncthreads();
#pragma unroll 2
        for (int dl = 0; dl < 32; dl++) {
            int d = dh * 32 + dl;
            float4 q4 = *(float4*)&qs[dl * 128 + sgrp * 4];
            float qv[4] = {q4.x, q4.y, q4.z, q4.w};
            float kss = ksums[d];
#pragma unroll
            for (int j = 0; j < 4; j++) den[j] += qv[j] * kss;
            float kvr[16];
#pragma unroll
            for (int c = 0; c < 4; c++)
                *(float4*)&kvr[c * 4] = *(float4*)&kvs[d * 64 + ech + c * 4];
#pragma unroll
            for (int j = 0; j < 4; j++)
#pragma unroll
                for (int e = 0; e < 16; e++)
                    num[j][e] += qv[j] * kvr[e];
        }
    }

    const int b = bh >> 4;
    const int h = bh & 15;
#pragma unroll
    for (int j = 0; j < 4; j++) {
        int s = s0 + sgrp * 4 + j;
        float inv = 1.f / (den[j] + 1e-6f);
        size_t base = ((size_t)(b * S_LEN + s)) * EMB + h * HD + ech;
        uint2 hi2[2], lo2[2];
#pragma unroll
        for (int c = 0; c < 2; c++) {
            float o0 = num[j][c * 8 + 0] * inv, o1 = num[j][c * 8 + 1] * inv;
            float o2 = num[j][c * 8 + 2] * inv, o3 = num[j][c * 8 + 3] * inv;
            float o4 = num[j][c * 8 + 4] * inv, o5 = num[j][c * 8 + 5] * inv;
            float o6 = num[j][c * 8 + 6] * inv, o7 = num[j][c * 8 + 7] * inv;
            __nv_bfloat162 h0 = __floats2bfloat162_rn(o0, o1);
            __nv_bfloat162 h1 = __floats2bfloat162_rn(o2, o3);
            __nv_bfloat162 h2 = __floats2bfloat162_rn(o4, o5);
            __nv_bfloat162 h3 = __floats2bfloat162_rn(o6, o7);
            float2 f0 = __bfloat1622float2(h0), f1 = __bfloat1622float2(h1);
            float2 f2 = __bfloat1622float2(h2), f3 = __bfloat1622float2(h3);
            __nv_bfloat162 l0 = __floats2bfloat162_rn(o0 - f0.x, o1 - f0.y);
            __nv_bfloat162 l1 = __floats2bfloat162_rn(o2 - f1.x, o3 - f1.y);
            __nv_bfloat162 l2 = __floats2bfloat162_rn(o4 - f2.x, o5 - f2.y);
            __nv_bfloat162 l3 = __floats2bfloat162_rn(o6 - f3.x, o7 - f3.y);
            hi2[0].x = *(uint32_t*)&h0; hi2[0].y = *(uint32_t*)&h1;
            hi2[1].x = *(uint32_t*)&h2; hi2[1].y = *(uint32_t*)&h3;
            lo2[0].x = *(uint32_t*)&l0; lo2[0].y = *(uint32_t*)&l1;
            lo2[1].x = *(uint32_t*)&l2; lo2[1].y = *(uint32_t*)&l3;
            *(uint2*)(g_ah + base + c * 8)     = hi2[0];
            *(uint2*)(g_ah + base + c * 8 + 4) = hi2[1];
            *(uint2*)(g_al + base + c * 8)     = lo2[0];
            *(uint2*)(g_al + base + c * 8 + 4) = lo2[1];
        }
    }
}

// ---------------------------------------------------------------------------
// launch
// ---------------------------------------------------------------------------
extern "C" void kernel_launch(void* const* d_in, const int* in_sizes, int n_in,
                              void* d_out, int out_size)
{
    const float* x  = (const float*)d_in[0];
    const float* Wq = (const float*)d_in[1];
    const float* bq = (const float*)d_in[2];
    const float* Wk = (const float*)d_in[3];
    const float* bk = (const float*)d_in[4];
    const float* Wv = (const float*)d_in[5];
    const float* bv = (const float*)d_in[6];
    const float* Wo = (const float*)d_in[7];
    const float* bo = (const float*)d_in[8];
    float* out = (float*)d_out;

    float *pq, *pk, *pv;
    __nv_bfloat16 *pxh, *pxl, *pah, *pal, *pwh, *pwl;
    cudaGetSymbolAddress((void**)&pq,  g_q);
    cudaGetSymbolAddress((void**)&pk,  g_k);
    cudaGetSymbolAddress((void**)&pv,  g_v);
    cudaGetSymbolAddress((void**)&pxh, g_xh);
    cudaGetSymbolAddress((void**)&pxl, g_xl);
    cudaGetSymbolAddress((void**)&pah, g_ah);
    cudaGetSymbolAddress((void**)&pal, g_al);
    cudaGetSymbolAddress((void**)&pwh, g_wh);
    cudaGetSymbolAddress((void**)&pwl, g_wl);

    cudaFuncSetAttribute(mma_gemm<1, true >, cudaFuncAttributeMaxDynamicSharedMemorySize, SMEM_DYN);
    cudaFuncSetAttribute(mma_gemm<1, false>, cudaFuncAttributeMaxDynamicSharedMemorySize, SMEM_DYN);
    cudaFuncSetAttribute(mma_gemm<0, false>, cudaFuncAttributeMaxDynamicSharedMemorySize, SMEM_DYN);

    const int NX4 = M_TOK * EMB / 4;       // 4194304
    const int NW4 = EMB * EMB / 4;         // 262144
    const size_t WSZ = (size_t)EMB * EMB;  // 1048576

    zero_kv_kernel<<<(BH * HD * HD + 255) / 256, 256>>>();

    cvt_split<<<NX4 / 256, 256>>>((const float4*)x, (uint2*)pxh, (uint2*)pxl, NX4);
    cvt_split<<<NW4 / 256, 256>>>((const float4*)Wq, (uint2*)(pwh + 0 * WSZ), (uint2*)(pwl + 0 * WSZ), NW4);
    cvt_split<<<NW4 / 256, 256>>>((const float4*)Wk, (uint2*)(pwh + 1 * WSZ), (uint2*)(pwl + 1 * WSZ), NW4);
    cvt_split<<<NW4 / 256, 256>>>((const float4*)Wv, (uint2*)(pwh + 2 * WSZ), (uint2*)(pwl + 2 * WSZ), NW4);
    cvt_split<<<NW4 / 256, 256>>>((const float4*)Wo, (uint2*)(pwh + 3 * WSZ), (uint2*)(pwl + 3 * WSZ), NW4);

    dim3 gg(EMB / 256, M_TOK / 128);   // (4, 128)

    mma_gemm<1, true ><<<gg, 256, SMEM_DYN>>>(pxh, pxl, pwh + 0 * WSZ, pwl + 0 * WSZ, bq, pq);
    mma_gemm<1, true ><<<gg, 256, SMEM_DYN>>>(pxh, pxl, pwh + 1 * WSZ, pwl + 1 * WSZ, bk, pk);
    mma_gemm<1, false><<<gg, 256, SMEM_DYN>>>(pxh, pxl, pwh + 2 * WSZ, pwl + 2 * WSZ, bv, pv);

    kv_kernel<<<dim3(BH, KV_SPLIT), 256>>>();

    attn_kernel<<<dim3(S_LEN / 128, BH), 128>>>();

    mma_gemm<0, false><<<gg, 256, SMEM_DYN>>>(pah, pal, pwh + 3 * WSZ, pwl + 3 * WSZ, bo, out);
}

// round 9
// speedup vs baseline: 1.0029x; 1.0029x over previous
#include <cuda_runtime.h>
#include <cuda_bf16.h>
#include <cstdint>
#include <math.h>

// Problem constants
#define BATCH   4
#define S_LEN   4096
#define EMB     1024
#define HEADS   16
#define HD      64
#define M_TOK   (BATCH * S_LEN)   // 16384
#define BH      (BATCH * HEADS)   // 64
#define KV_SPLIT 8

// ---------------------------------------------------------------------------
// Scratch (device globals: allocation-free, rule-compliant)
// ---------------------------------------------------------------------------
__device__ float g_q[(size_t)BH * S_LEN * HD];     // [b,h,s,d] phi(q)
__device__ float g_k[(size_t)BH * S_LEN * HD];     // [b,h,s,d] phi(k)
__device__ float g_v[(size_t)BH * S_LEN * HD];     // [b,h,s,d] v
__device__ float g_KV[BH * HD * HD];               // [bh, d, e]
__device__ float g_Ksum[BH * HD];                  // [bh, d]

// split-precision bf16 buffers
__device__ __nv_bfloat16 g_xh[(size_t)M_TOK * EMB];
__device__ __nv_bfloat16 g_xl[(size_t)M_TOK * EMB];
__device__ __nv_bfloat16 g_ah[(size_t)M_TOK * EMB];   // attn out hi (token-major)
__device__ __nv_bfloat16 g_al[(size_t)M_TOK * EMB];   // attn out lo
__device__ __nv_bfloat16 g_wh[(size_t)4 * EMB * EMB]; // Wq,Wk,Wv,Wo hi
__device__ __nv_bfloat16 g_wl[(size_t)4 * EMB * EMB]; // Wq,Wk,Wv,Wo lo

// ---------------------------------------------------------------------------
// PTX helpers (sm_100 base target: cp.async / ldmatrix / mma.sync only)
// ---------------------------------------------------------------------------
__device__ __forceinline__ uint32_t smem_u32(const void* p) {
    uint32_t a;
    asm("{ .reg .u64 t; cvta.to.shared.u64 t, %1; cvt.u32.u64 %0, t; }"
        : "=r"(a) : "l"(p));
    return a;
}

__device__ __forceinline__ void cp16(uint32_t dst, const void* src) {
    asm volatile("cp.async.cg.shared.global [%0], [%1], 16;"
                 :: "r"(dst), "l"(src));
}
#define CP_COMMIT()  asm volatile("cp.async.commit_group;" ::: "memory")
#define CP_WAIT2()   asm volatile("cp.async.wait_group 2;" ::: "memory")

__device__ __forceinline__ void ldsm4(uint32_t* r, uint32_t addr) {
    asm volatile("ldmatrix.sync.aligned.m8n8.x4.shared.b16 {%0,%1,%2,%3}, [%4];"
                 : "=r"(r[0]), "=r"(r[1]), "=r"(r[2]), "=r"(r[3]) : "r"(addr));
}

__device__ __forceinline__ void mma_bf16(float* c, const uint32_t* a, const uint32_t* b) {
    asm volatile(
        "mma.sync.aligned.m16n8k16.row.col.f32.bf16.bf16.f32 "
        "{%0,%1,%2,%3}, {%4,%5,%6,%7}, {%8,%9}, {%0,%1,%2,%3};"
        : "+f"(c[0]), "+f"(c[1]), "+f"(c[2]), "+f"(c[3])
        : "r"(a[0]), "r"(a[1]), "r"(a[2]), "r"(a[3]), "r"(b[0]), "r"(b[1]));
}

// ---------------------------------------------------------------------------
// fp32 -> (hi, lo) bf16 split conversion (grid-stride over float4)
// ---------------------------------------------------------------------------
__global__ void cvt_split(const float4* __restrict__ in,
                          uint2* __restrict__ hi, uint2* __restrict__ lo, int n4)
{
    int i = blockIdx.x * blockDim.x + threadIdx.x;
    if (i >= n4) return;
    float4 v = in[i];
    __nv_bfloat162 h0 = __floats2bfloat162_rn(v.x, v.y);
    __nv_bfloat162 h1 = __floats2bfloat162_rn(v.z, v.w);
    float2 f0 = __bfloat1622float2(h0);
    float2 f1 = __bfloat1622float2(h1);
    __nv_bfloat162 l0 = __floats2bfloat162_rn(v.x - f0.x, v.y - f0.y);
    __nv_bfloat162 l1 = __floats2bfloat162_rn(v.z - f1.x, v.w - f1.y);
    uint2 hu, lu;
    hu.x = *(uint32_t*)&h0; hu.y = *(uint32_t*)&h1;
    lu.x = *(uint32_t*)&l0; lu.y = *(uint32_t*)&l1;
    hi[i] = hu;
    lo[i] = lu;
}

// ---------------------------------------------------------------------------
// mma.sync split-bf16 GEMM (TN): C = A[M,1024] * W[N,1024]^T + bias (+phi)
// CTA 128x256, 8 warps (warp tile 64x64, 2x4 warp grid), BK=32,
// 3-stage cp.async pipeline.
// smem per stage: Ah(128x80) Al(128x80) Wh(256x80) Wl(256x80) = 61440 B.
// OUTMODE 0: token-major.  OUTMODE 1: scatter to [b,h,s,d].
// ---------------------------------------------------------------------------
#define ROWB     80
#define A_TILE   (128 * ROWB)                  // 10240
#define W_TILE   (256 * ROWB)                  // 20480
#define STG_BYTES (2 * A_TILE + 2 * W_TILE)    // 61440
#define SMEM_DYN (3 * STG_BYTES)               // 184320

__device__ __forceinline__ void load_stage(
    uint32_t smem_base, int st, int kt,
    const __nv_bfloat16* __restrict__ Ahb, const __nv_bfloat16* __restrict__ Alb,
    const __nv_bfloat16* __restrict__ Whb, const __nv_bfloat16* __restrict__ Wlb,
    int tid)
{
    uint32_t sb = smem_base + st * STG_BYTES;
    const int koff = kt * 32;
    // A tiles: 128 rows x 4 cp16, hi then lo (512 cp16 each -> 2 reps)
#pragma unroll
    for (int rep = 0; rep < 2; rep++) {
        int id  = tid + rep * 256;
        int row = id >> 2;
        int c   = id & 3;
        cp16(sb + row * ROWB + c * 16,          Ahb + (size_t)row * EMB + koff + c * 8);
        cp16(sb + A_TILE + row * ROWB + c * 16, Alb + (size_t)row * EMB + koff + c * 8);
    }
    // W tiles: 256 rows x 4 cp16, hi then lo (1024 cp16 each -> 4 reps)
    uint32_t wb = sb + 2 * A_TILE;
#pragma unroll
    for (int rep = 0; rep < 4; rep++) {
        int id  = tid + rep * 256;
        int row = id >> 2;
        int c   = id & 3;
        cp16(wb + row * ROWB + c * 16,          Whb + (size_t)row * EMB + koff + c * 8);
        cp16(wb + W_TILE + row * ROWB + c * 16, Wlb + (size_t)row * EMB + koff + c * 8);
    }
}

__device__ __forceinline__ void compute_k16(
    uint32_t sa, int k16, int wm, int wn, int lane, float acc[4][8][4])
{
    uint32_t a_h[4][4], a_l[4][4];
    const uint32_t arow = (uint32_t)(wm + (lane & 15));
    const uint32_t acol = (uint32_t)(k16 * 16 + (lane >> 4) * 8) * 2;
#pragma unroll
    for (int mt = 0; mt < 4; mt++) {
        uint32_t ad = sa + (arow + mt * 16) * ROWB + acol;
        ldsm4(a_h[mt], ad);
        ldsm4(a_l[mt], ad + A_TILE);
    }
    const uint32_t wbase = sa + 2 * A_TILE;
    const uint32_t brow = (uint32_t)(wn + ((lane >> 4) * 8) + (lane & 7));
    const uint32_t bcol = (uint32_t)(k16 * 16 + ((lane >> 3) & 1) * 8) * 2;
#pragma unroll
    for (int nt2 = 0; nt2 < 4; nt2++) {
        uint32_t bh[4], bl[4];
        uint32_t bd = wbase + (brow + nt2 * 16) * ROWB + bcol;
        ldsm4(bh, bd);
        ldsm4(bl, bd + W_TILE);
#pragma unroll
        for (int mt = 0; mt < 4; mt++) {
            mma_bf16(acc[mt][nt2 * 2],     a_h[mt], bh);
            mma_bf16(acc[mt][nt2 * 2],     a_h[mt], bl);
            mma_bf16(acc[mt][nt2 * 2],     a_l[mt], bh);
            mma_bf16(acc[mt][nt2 * 2 + 1], a_h[mt], bh + 2);
            mma_bf16(acc[mt][nt2 * 2 + 1], a_h[mt], bl + 2);
            mma_bf16(acc[mt][nt2 * 2 + 1], a_l[mt], bh + 2);
        }
    }
}

template <int OUTMODE, bool PHI>
__global__ void __launch_bounds__(256, 1) mma_gemm(
    const __nv_bfloat16* __restrict__ Ah, const __nv_bfloat16* __restrict__ Al,
    const __nv_bfloat16* __restrict__ Wh, const __nv_bfloat16* __restrict__ Wl,
    const float* __restrict__ bias, float* __restrict__ C)
{
    extern __shared__ char smem[];
    const uint32_t smem_base = smem_u32(smem);
    const int tid  = threadIdx.x;
    const int wid  = tid >> 5;
    const int lane = tid & 31;
    const int bm = blockIdx.y * 128;
    const int bn = blockIdx.x * 256;
    const int wm = (wid & 1) * 64;       // 2 warps in M
    const int wn = (wid >> 1) * 64;      // 4 warps in N

    const __nv_bfloat16* Ahb = Ah + (size_t)bm * EMB;
    const __nv_bfloat16* Alb = Al + (size_t)bm * EMB;
    const __nv_bfloat16* Whb = Wh + (size_t)bn * EMB;
    const __nv_bfloat16* Wlb = Wl + (size_t)bn * EMB;

    float acc[4][8][4] = {};

    // prologue: stages 0,1 for ktiles 0,1
    load_stage(smem_base, 0, 0, Ahb, Alb, Whb, Wlb, tid);
    CP_COMMIT();
    load_stage(smem_base, 1, 1, Ahb, Alb, Whb, Wlb, tid);
    CP_COMMIT();

    const int NKT = EMB / 32;   // 32
    for (int kt = 0; kt < NKT; kt++) {
        if (kt + 2 < NKT)
            load_stage(smem_base, (kt + 2) % 3, kt + 2, Ahb, Alb, Whb, Wlb, tid);
        CP_COMMIT();
        CP_WAIT2();
        __syncthreads();
        uint32_t sa = smem_base + (kt % 3) * STG_BYTES;
        compute_k16(sa, 0, wm, wn, lane, acc);
        compute_k16(sa, 1, wm, wn, lane, acc);
        __syncthreads();
    }

    // epilogue: bias (+phi), store from register accumulators
    const int ln4 = lane >> 2;
    const int lc  = (lane & 3) * 2;
#pragma unroll
    for (int mt = 0; mt < 4; mt++) {
#pragma unroll
        for (int half = 0; half < 2; half++) {
            int m  = bm + wm + mt * 16 + ln4 + half * 8;
            int bb = m >> 12;                // batch (S_LEN=4096)
            int s  = m & (S_LEN - 1);
#pragma unroll
            for (int nt = 0; nt < 8; nt++) {
                int n = bn + wn + nt * 8 + lc;
                float2 bv = *(const float2*)(bias + n);
                float vx = acc[mt][nt][half * 2 + 0] + bv.x;
                float vy = acc[mt][nt][half * 2 + 1] + bv.y;
                if (PHI) {
                    vx = (vx > 0.f) ? vx + 1.f : __expf(vx);
                    vy = (vy > 0.f) ? vy + 1.f : __expf(vy);
                }
                float2 r = make_float2(vx, vy);
                if (OUTMODE == 0) {
                    *(float2*)(C + (size_t)m * EMB + n) = r;
                } else {
                    int h = n >> 6, d = n & 63;
                    *(float2*)(C + (((size_t)(bb * HEADS + h)) * S_LEN + s) * HD + d) = r;
                }
            }
        }
    }
}

// ---------------------------------------------------------------------------
// Zero the KV / Ksum accumulators (device globals persist across graph replays)
// ---------------------------------------------------------------------------
__global__ void zero_kv_kernel()
{
    int i = blockIdx.x * blockDim.x + threadIdx.x;
    if (i < BH * HD * HD) g_KV[i] = 0.f;
    if (i < BH * HD)      g_Ksum[i] = 0.f;
}

// ---------------------------------------------------------------------------
// KV[bh,d,e] = sum_s k_phi[s,d] * v[s,e];  Ksum[bh,d] = sum_s k_phi[s,d]
// ---------------------------------------------------------------------------
__global__ void __launch_bounds__(256) kv_kernel()
{
    const int bh    = blockIdx.x;
    const int split = blockIdx.y;
    const int tid   = threadIdx.x;
    const int te    = tid & 15;
    const int td    = tid >> 4;

    __shared__ float ks[32][64];
    __shared__ float vs[32][64];

    float acc[4][4] = {};
    float ksum[4]   = {};

    const float* kp = g_k + (size_t)bh * S_LEN * HD;
    const float* vp = g_v + (size_t)bh * S_LEN * HD;

    const int sBeg = split * (S_LEN / KV_SPLIT);
    const int sEnd = sBeg + (S_LEN / KV_SPLIT);

    for (int s0 = sBeg; s0 < sEnd; s0 += 32) {
#pragma unroll
        for (int i = 0; i < 2; i++) {
            int id  = tid + i * 256;
            int row = id >> 4;
            int c4  = (id & 15) * 4;
            *(float4*)&ks[row][c4] = *(const float4*)(kp + (size_t)(s0 + row) * HD + c4);
            *(float4*)&vs[row][c4] = *(const float4*)(vp + (size_t)(s0 + row) * HD + c4);
        }
        __syncthreads();
#pragma unroll 4
        for (int s = 0; s < 32; s++) {
            float4 k4 = *(float4*)&ks[s][td * 4];
            float4 v4 = *(float4*)&vs[s][te * 4];
            float kd[4] = {k4.x, k4.y, k4.z, k4.w};
            float ve[4] = {v4.x, v4.y, v4.z, v4.w};
#pragma unroll
            for (int i = 0; i < 4; i++)
#pragma unroll
                for (int j = 0; j < 4; j++)
                    acc[i][j] += kd[i] * ve[j];
            if (te == 0) {
#pragma unroll
                for (int i = 0; i < 4; i++) ksum[i] += kd[i];
            }
        }
        __syncthreads();
    }

    float* kvout = g_KV + (size_t)bh * HD * HD;
#pragma unroll
    for (int i = 0; i < 4; i++)
#pragma unroll
        for (int j = 0; j < 4; j++)
            atomicAdd(&kvout[(td * 4 + i) * HD + te * 4 + j], acc[i][j]);
    if (te == 0) {
#pragma unroll
        for (int i = 0; i < 4; i++)
            atomicAdd(&g_Ksum[bh * HD + td * 4 + i], ksum[i]);
    }
}

// ---------------------------------------------------------------------------
// attn: out = (q_phi @ KV) / (q_phi @ Ksum + eps), written directly as
// split hi/lo bf16 into g_ah/g_al (token-major), feeding the final GEMM.
// ---------------------------------------------------------------------------
__global__ void __launch_bounds__(128) attn_kernel()
{
    const int bh  = blockIdx.y;
    const int s0  = blockIdx.x * 128;
    const int tid = threadIdx.x;
    const int sgrp = tid >> 2;
    const int ech  = (tid & 3) * 16;

    __shared__ float qs[32 * 128];
    __shared__ float kvs[64 * 64];
    __shared__ float ksums[64];

#pragma unroll
    for (int i = 0; i < 8; i++) {
        int id = tid + i * 128;
        *(float4*)&kvs[id * 4] = *(const float4*)(g_KV + (size_t)bh * HD * HD + id * 4);
    }
    if (tid < 64) ksums[tid] = g_Ksum[bh * HD + tid];

    float num[4][16] = {};
    float den[4]     = {};

    const float* qp = g_q + ((size_t)bh * S_LEN + s0) * HD;

    for (int dh = 0; dh < 2; dh++) {
        __syncthreads();
#pragma unroll
        for (int i = 0; i < 8; i++) {
            int id  = tid + i * 128;
            int row = id >> 3;
            int c4  = (id & 7) * 4;
            float4 qv = *(const float4*)(qp + (size_t)row * HD + dh * 32 + c4);
            qs[(c4 + 0) * 128 + row] = qv.x;
            qs[(c4 + 1) * 128 + row] = qv.y;
            qs[(c4 + 2) * 128 + row] = qv.z;
            qs[(c4 + 3) * 128 + row] = qv.w;
        }
        __syncthreads();
#pragma unroll 2
        for (int dl = 0; dl < 32; dl++) {
            int d = dh * 32 + dl;
            float4 q4 = *(float4*)&qs[dl * 128 + sgrp * 4];
            float qv[4] = {q4.x, q4.y, q4.z, q4.w};
            float kss = ksums[d];
#pragma unroll
            for (int j = 0; j < 4; j++) den[j] += qv[j] * kss;
            float kvr[16];
#pragma unroll
            for (int c = 0; c < 4; c++)
                *(float4*)&kvr[c * 4] = *(float4*)&kvs[d * 64 + ech + c * 4];
#pragma unroll
            for (int j = 0; j < 4; j++)
#pragma unroll
                for (int e = 0; e < 16; e++)
                    num[j][e] += qv[j] * kvr[e];
        }
    }

    const int b = bh >> 4;
    const int h = bh & 15;
#pragma unroll
    for (int j = 0; j < 4; j++) {
        int s = s0 + sgrp * 4 + j;
        float inv = 1.f / (den[j] + 1e-6f);
        size_t base = ((size_t)(b * S_LEN + s)) * EMB + h * HD + ech;
        uint2 hi2[2], lo2[2];
#pragma unroll
        for (int c = 0; c < 2; c++) {
            float o0 = num[j][c * 8 + 0] * inv, o1 = num[j][c * 8 + 1] * inv;
            float o2 = num[j][c * 8 + 2] * inv, o3 = num[j][c * 8 + 3] * inv;
            float o4 = num[j][c * 8 + 4] * inv, o5 = num[j][c * 8 + 5] * inv;
            float o6 = num[j][c * 8 + 6] * inv, o7 = num[j][c * 8 + 7] * inv;
            __nv_bfloat162 h0 = __floats2bfloat162_rn(o0, o1);
            __nv_bfloat162 h1 = __floats2bfloat162_rn(o2, o3);
            __nv_bfloat162 h2 = __floats2bfloat162_rn(o4, o5);
            __nv_bfloat162 h3 = __floats2bfloat162_rn(o6, o7);
            float2 f0 = __bfloat1622float2(h0), f1 = __bfloat1622float2(h1);
            float2 f2 = __bfloat1622float2(h2), f3 = __bfloat1622float2(h3);
            __nv_bfloat162 l0 = __floats2bfloat162_rn(o0 - f0.x, o1 - f0.y);
            __nv_bfloat162 l1 = __floats2bfloat162_rn(o2 - f1.x, o3 - f1.y);
            __nv_bfloat162 l2 = __floats2bfloat162_rn(o4 - f2.x, o5 - f2.y);
            __nv_bfloat162 l3 = __floats2bfloat162_rn(o6 - f3.x, o7 - f3.y);
            hi2[0].x = *(uint32_t*)&h0; hi2[0].y = *(uint32_t*)&h1;
            hi2[1].x = *(uint32_t*)&h2; hi2[1].y = *(uint32_t*)&h3;
            lo2[0].x = *(uint32_t*)&l0; lo2[0].y = *(uint32_t*)&l1;
            lo2[1].x = *(uint32_t*)&l2; lo2[1].y = *(uint32_t*)&l3;
            *(uint2*)(g_ah + base + c * 8)     = hi2[0];
            *(uint2*)(g_ah + base + c * 8 + 4) = hi2[1];
            *(uint2*)(g_al + base + c * 8)     = lo2[0];
            *(uint2*)(g_al + base + c * 8 + 4) = lo2[1];
        }
    }
}

// ---------------------------------------------------------------------------
// launch
// ---------------------------------------------------------------------------
extern "C" void kernel_launch(void* const* d_in, const int* in_sizes, int n_in,
                              void* d_out, int out_size)
{
    const float* x  = (const float*)d_in[0];
    const float* Wq = (const float*)d_in[1];
    const float* bq = (const float*)d_in[2];
    const float* Wk = (const float*)d_in[3];
    const float* bk = (const float*)d_in[4];
    const float* Wv = (const float*)d_in[5];
    const float* bv = (const float*)d_in[6];
    const float* Wo = (const float*)d_in[7];
    const float* bo = (const float*)d_in[8];
    float* out = (float*)d_out;

    float *pq, *pk, *pv;
    __nv_bfloat16 *pxh, *pxl, *pah, *pal, *pwh, *pwl;
    cudaGetSymbolAddress((void**)&pq,  g_q);
    cudaGetSymbolAddress((void**)&pk,  g_k);
    cudaGetSymbolAddress((void**)&pv,  g_v);
    cudaGetSymbolAddress((void**)&pxh, g_xh);
    cudaGetSymbolAddress((void**)&pxl, g_xl);
    cudaGetSymbolAddress((void**)&pah, g_ah);
    cudaGetSymbolAddress((void**)&pal, g_al);
    cudaGetSymbolAddress((void**)&pwh, g_wh);
    cudaGetSymbolAddress((void**)&pwl, g_wl);

    cudaFuncSetAttribute(mma_gemm<1, true >, cudaFuncAttributeMaxDynamicSharedMemorySize, SMEM_DYN);
    cudaFuncSetAttribute(mma_gemm<1, false>, cudaFuncAttributeMaxDynamicSharedMemorySize, SMEM_DYN);
    cudaFuncSetAttribute(mma_gemm<0, false>, cudaFuncAttributeMaxDynamicSharedMemorySize, SMEM_DYN);

    const int NX4 = M_TOK * EMB / 4;       // 4194304
    const int NW4 = EMB * EMB / 4;         // 262144
    const size_t WSZ = (size_t)EMB * EMB;  // 1048576

    zero_kv_kernel<<<(BH * HD * HD + 255) / 256, 256>>>();

    cvt_split<<<NX4 / 256, 256>>>((const float4*)x, (uint2*)pxh, (uint2*)pxl, NX4);
    cvt_split<<<NW4 / 256, 256>>>((const float4*)Wq, (uint2*)(pwh + 0 * WSZ), (uint2*)(pwl + 0 * WSZ), NW4);
    cvt_split<<<NW4 / 256, 256>>>((const float4*)Wk, (uint2*)(pwh + 1 * WSZ), (uint2*)(pwl + 1 * WSZ), NW4);
    cvt_split<<<NW4 / 256, 256>>>((const float4*)Wv, (uint2*)(pwh + 2 * WSZ), (uint2*)(pwl + 2 * WSZ), NW4);
    cvt_split<<<NW4 / 256, 256>>>((const float4*)Wo, (uint2*)(pwh + 3 * WSZ), (uint2*)(pwl + 3 * WSZ), NW4);

    dim3 gg(EMB / 256, M_TOK / 128);   // (4, 128)

    mma_gemm<1, true ><<<gg, 256, SMEM_DYN>>>(pxh, pxl, pwh + 0 * WSZ, pwl + 0 * WSZ, bq, pq);
    mma_gemm<1, true ><<<gg, 256, SMEM_DYN>>>(pxh, pxl, pwh + 1 * WSZ, pwl + 1 * WSZ, bk, pk);
    mma_gemm<1, false><<<gg, 256, SMEM_DYN>>>(pxh, pxl, pwh + 2 * WSZ, pwl + 2 * WSZ, bv, pv);

    kv_kernel<<<dim3(BH, KV_SPLIT), 256>>>();

    attn_kernel<<<dim3(S_LEN / 128, BH), 128>>>();

    mma_gemm<0, false><<<gg, 256, SMEM_DYN>>>(pah, pal, pwh + 3 * WSZ, pwl + 3 * WSZ, bo, out);
}